// round 6
// baseline (speedup 1.0000x reference)
#include <cuda_runtime.h>
#include <math.h>
#include <stdint.h>

#define BSZ 8
#define SEQ 100
#define IND 768
#define HID 512
#define NHD 8
#define DK  64
#define MROWS (BSZ*SEQ)   // 800

// ---------------- scratch ------------------------------------------------------
__device__ float g_sx0[MROWS*HID];
__device__ float g_ax0[MROWS*HID];
__device__ float g_sx [MROWS*HID];
__device__ float g_ax [MROWS*HID];
__device__ float g_us [MROWS*HID];
__device__ float g_vs [MROWS*HID];
__device__ float g_ua [MROWS*HID];
__device__ float g_va [MROWS*HID];
__device__ float g_PTs[200*HID];
__device__ float g_PTa[200*HID];
__device__ float g_As [BSZ*NHD*SEQ*SEQ];
__device__ float g_Aa [BSZ*NHD*SEQ*SEQ];
__device__ float g_qkv[2*MROWS*3072];
__device__ float g_att[4*MROWS*HID];
__device__ float g_opj[4*MROWS*HID];

// ---------------- tf32 helpers -------------------------------------------------
__device__ __forceinline__ void tf32split(float x, float& hi, float& lo) {
    uint32_t h;
    asm("cvt.rna.tf32.f32 %0, %1;" : "=r"(h) : "f"(x));
    hi = __uint_as_float(h);
    float r = x - hi;
    uint32_t l2;
    asm("cvt.rna.tf32.f32 %0, %1;" : "=r"(l2) : "f"(r));
    lo = __uint_as_float(l2);
}

#define MMA8(d, a, b) \
    asm volatile("mma.sync.aligned.m16n8k8.row.col.f32.tf32.tf32.f32 " \
        "{%0,%1,%2,%3}, {%4,%5,%6,%7}, {%8,%9}, {%0,%1,%2,%3};" \
        : "+f"((d)[0]), "+f"((d)[1]), "+f"((d)[2]), "+f"((d)[3]) \
        : "r"((a)[0]), "r"((a)[1]), "r"((a)[2]), "r"((a)[3]), \
          "r"((b)[0]), "r"((b)[1]))

// ---------------- batched pointer sets -----------------------------------------
struct GemmSet  { const float* A; const float* B; const float* bias; float* C; float* C2; };
struct GemmSets { GemmSet s[4]; };

// ---------------- tensor-core GEMM (3xTF32), depth-2 prefetch -------------------
#define PAS 73
#define PBS 67

__global__ void __launch_bounds__(128)
gemm_tc(GemmSets sets, int M, int N, int K)
{
    GemmSet gsel = sets.s[blockIdx.z];
    const float* __restrict__ A = gsel.A;
    const float* __restrict__ B = gsel.B;
    const float* __restrict__ bias = gsel.bias;
    float* __restrict__ C  = gsel.C;
    float* __restrict__ C2 = gsel.C2;

    __shared__ float2 smA[2][16*PAS];
    __shared__ float2 smB[2][16*PBS];

    const int tid = threadIdx.x;
    const int lane = tid & 31, warp = tid >> 5;
    const int wM = warp >> 1, wN = warp & 1;
    const int t4 = lane & 3, g8 = lane >> 2;
    const int row0 = blockIdx.y * 64, col0 = blockIdx.x * 64;

    float acc[2][4][4];
    #pragma unroll
    for (int mt = 0; mt < 2; mt++)
        #pragma unroll
        for (int nt = 0; nt < 4; nt++)
            #pragma unroll
            for (int e = 0; e < 4; e++) acc[mt][nt][e] = 0.f;

    const int KT = K >> 4;
    float4 avA[2][2], avB[2][2];

#define LOAD_T(set, kt) { \
        int k0 = (kt) << 4; \
        _Pragma("unroll") \
        for (int l = 0; l < 2; l++) { \
            int f = tid + (l << 7); \
            int r = f >> 2, kq = f & 3; \
            int gr = row0 + r; \
            avA[set][l] = (gr < M) ? *(const float4*)(A + (long)gr * K + k0 + (kq << 2)) \
                                   : make_float4(0.f, 0.f, 0.f, 0.f); \
            int kr = f >> 4, nq = f & 15; \
            int gn = col0 + (nq << 2); \
            int gidx = gn >> 9; \
            avB[set][l] = *(const float4*)(B + (long)gidx * K * 512 + (long)(k0 + kr) * 512 + (gn & 511)); \
        } }

#define STORE_T(set, buf) { \
        float2* sA = smA[buf]; float2* sB = smB[buf]; \
        _Pragma("unroll") \
        for (int l = 0; l < 2; l++) { \
            int f = tid + (l << 7); \
            int r = f >> 2, kq = f & 3; \
            float ea[4] = {avA[set][l].x, avA[set][l].y, avA[set][l].z, avA[set][l].w}; \
            _Pragma("unroll") \
            for (int e = 0; e < 4; e++) { \
                int k = (kq << 2) + e; \
                float hi, lo; tf32split(ea[e], hi, lo); \
                sA[k * PAS + r] = make_float2(hi, lo); \
            } \
            int kr = f >> 4, nb = (f & 15) << 2; \
            float eb[4] = {avB[set][l].x, avB[set][l].y, avB[set][l].z, avB[set][l].w}; \
            _Pragma("unroll") \
            for (int e = 0; e < 4; e++) { \
                float hi, lo; tf32split(eb[e], hi, lo); \
                sB[kr * PBS + nb + e] = make_float2(hi, lo); \
            } \
        } }

#define COMPUTE_T(buf) { \
        const float2* sA = smA[buf]; const float2* sB = smB[buf]; \
        _Pragma("unroll") \
        for (int ks = 0; ks < 16; ks += 8) { \
            int kb = ks + t4; \
            uint32_t ah[2][4], al[2][4], bh[4][2], bl[4][2]; \
            _Pragma("unroll") \
            for (int mt = 0; mt < 2; mt++) { \
                int bm = wM * 32 + mt * 16 + g8; \
                float2 p0 = sA[kb * PAS + bm]; \
                float2 p1 = sA[kb * PAS + bm + 8]; \
                float2 p2 = sA[(kb + 4) * PAS + bm]; \
                float2 p3 = sA[(kb + 4) * PAS + bm + 8]; \
                ah[mt][0] = __float_as_uint(p0.x); al[mt][0] = __float_as_uint(p0.y); \
                ah[mt][1] = __float_as_uint(p1.x); al[mt][1] = __float_as_uint(p1.y); \
                ah[mt][2] = __float_as_uint(p2.x); al[mt][2] = __float_as_uint(p2.y); \
                ah[mt][3] = __float_as_uint(p3.x); al[mt][3] = __float_as_uint(p3.y); \
            } \
            _Pragma("unroll") \
            for (int nt = 0; nt < 4; nt++) { \
                int bn = wN * 32 + nt * 8 + g8; \
                float2 q0 = sB[kb * PBS + bn]; \
                float2 q1 = sB[(kb + 4) * PBS + bn]; \
                bh[nt][0] = __float_as_uint(q0.x); bl[nt][0] = __float_as_uint(q0.y); \
                bh[nt][1] = __float_as_uint(q1.x); bl[nt][1] = __float_as_uint(q1.y); \
            } \
            _Pragma("unroll") \
            for (int mt = 0; mt < 2; mt++) \
                _Pragma("unroll") \
                for (int nt = 0; nt < 4; nt++) { \
                    MMA8(acc[mt][nt], ah[mt], bh[nt]); \
                    MMA8(acc[mt][nt], ah[mt], bl[nt]); \
                    MMA8(acc[mt][nt], al[mt], bh[nt]); \
                } \
        } }

    LOAD_T(0, 0);
    if (KT > 1) LOAD_T(1, 1);
    STORE_T(0, 0);
    __syncthreads();

    #pragma unroll 1
    for (int kt = 0; kt < KT; kt++) {
        int cur = kt & 1;
        if (kt + 2 < KT) LOAD_T(cur, kt + 2);
        COMPUTE_T(cur);
        if (kt + 1 < KT) STORE_T((kt + 1) & 1, (kt + 1) & 1);
        __syncthreads();
    }

    #pragma unroll
    for (int mt = 0; mt < 2; mt++) {
        int rbase = row0 + wM * 32 + mt * 16;
        #pragma unroll
        for (int nt = 0; nt < 4; nt++) {
            int cbase = col0 + wN * 32 + nt * 8;
            #pragma unroll
            for (int e = 0; e < 4; e++) {
                int r = rbase + g8 + ((e >= 2) ? 8 : 0);
                int c = cbase + t4 * 2 + (e & 1);
                if (r < M) {
                    float v = acc[mt][nt][e];
                    if (bias) v += bias[c];
                    C[(long)r * N + c] = v;
                    if (C2) C2[(long)r * N + c] = v;
                }
            }
        }
    }
#undef LOAD_T
#undef STORE_T
#undef COMPUTE_T
}

// ---------------- u/v projections ----------------------------------------------
__global__ void uv_kernel(const float* __restrict__ sent_logits,
                          const float* __restrict__ act_logits,
                          const float* __restrict__ sgw1,
                          const float* __restrict__ agw1)
{
    int row = blockIdx.x;
    int t = threadIdx.x;
    __shared__ float p[19];
    if (t < 7) p[t] = sent_logits[row * 7 + t];
    else if (t < 19) p[t] = act_logits[row * 12 + (t - 7)];
    __syncthreads();
    float us = 0.f, vs = 0.f, ua = 0.f, va = 0.f;
    #pragma unroll
    for (int k = 0; k < 19; k++) {
        float pk = p[k];
        us += pk * sgw1[k * HID + t];
        vs += pk * sgw1[(19 + k) * HID + t];
        ua += pk * agw1[k * HID + t];
        va += pk * agw1[(19 + k) * HID + t];
    }
    g_us[row * HID + t] = us;
    g_vs[row * HID + t] = vs;
    g_ua[row * HID + t] = ua;
    g_va[row * HID + t] = va;
}

// ---------------- edge-weight generator (i-tiled, vectorized) -------------------
// grid (SEQ/GIT, BSZ, 2 gens), block 256 = 8 warps (warp owns j, strided by 8).
// acc[i][h] per lane over its 16 k's; shfl-reduce; sigmoid on lane 0.
// w2 in smem with stride 9 -> conflict-free LDS.128 (lane*36 words walks banks).
#define GIT 5

struct GenSet  { const float* u; const float* v; const float* PT;
                 const float* b1; const float* w2; const float* b2; float* Aout; };
struct GenSets { GenSet s[2]; };

__global__ void __launch_bounds__(256) genA_kernel(GenSets gsets)
{
    GenSet g = gsets.s[blockIdx.z];
    const int b  = blockIdx.y;
    const int i0 = blockIdx.x * GIT;

    __shared__ float ush[GIT * HID];
    __shared__ float w2s[HID * 9];
    __shared__ float b2s[NHD];

    const int t = threadIdx.x;
    for (int idx = t; idx < GIT * HID; idx += 256) {
        int i = idx >> 9, k = idx & 511;
        ush[idx] = g.u[(long)(b * SEQ + i0 + i) * HID + k] + g.b1[k];
    }
    for (int idx = t; idx < HID * NHD; idx += 256) {
        int k = idx >> 3, h = idx & 7;
        w2s[k * 9 + h] = g.w2[idx];
    }
    if (t < NHD) b2s[t] = g.b2[t];
    __syncthreads();

    const int warp = t >> 5, lane = t & 31;

    for (int j = warp; j < SEQ; j += 8) {
        const float* vrow = g.v + (long)(b * SEQ + j) * HID;
        float acc[GIT][NHD];
        #pragma unroll
        for (int i = 0; i < GIT; i++)
            #pragma unroll
            for (int h = 0; h < NHD; h++) acc[i][h] = 0.f;

        #pragma unroll
        for (int q = 0; q < 4; q++) {
            int k0 = q * 128 + lane * 4;
            float4 v4 = *(const float4*)(vrow + k0);
            float hv[GIT][4];
            #pragma unroll
            for (int i = 0; i < GIT; i++) {
                const float* pr = g.PT + (long)(j - (i0 + i) + 100) * HID;
                float4 p4 = *(const float4*)(pr + k0);
                float4 u4 = *(const float4*)(ush + i * HID + k0);
                hv[i][0] = fmaxf(u4.x + v4.x + p4.x, 0.f);
                hv[i][1] = fmaxf(u4.y + v4.y + p4.y, 0.f);
                hv[i][2] = fmaxf(u4.z + v4.z + p4.z, 0.f);
                hv[i][3] = fmaxf(u4.w + v4.w + p4.w, 0.f);
            }
            #pragma unroll
            for (int e = 0; e < 4; e++) {
                const float* wr = w2s + (k0 + e) * 9;
                float4 wa = *(const float4*)(wr);
                float4 wb = *(const float4*)(wr + 4);
                #pragma unroll
                for (int i = 0; i < GIT; i++) {
                    float hvv = hv[i][e];
                    acc[i][0] += hvv * wa.x; acc[i][1] += hvv * wa.y;
                    acc[i][2] += hvv * wa.z; acc[i][3] += hvv * wa.w;
                    acc[i][4] += hvv * wb.x; acc[i][5] += hvv * wb.y;
                    acc[i][6] += hvv * wb.z; acc[i][7] += hvv * wb.w;
                }
            }
        }

        #pragma unroll
        for (int i = 0; i < GIT; i++) {
            #pragma unroll
            for (int h = 0; h < NHD; h++) {
                float v = acc[i][h];
                v += __shfl_down_sync(0xffffffffu, v, 16);
                v += __shfl_down_sync(0xffffffffu, v, 8);
                v += __shfl_down_sync(0xffffffffu, v, 4);
                v += __shfl_down_sync(0xffffffffu, v, 2);
                v += __shfl_down_sync(0xffffffffu, v, 1);
                if (lane == 0) {
                    float s = v + b2s[h];
                    g.Aout[(((long)b * NHD + h) * SEQ + (i0 + i)) * SEQ + j] =
                        1.f / (1.f + __expf(-s));
                }
            }
        }
    }
}

// ---------------- attention: i-tiled, all heads per block ----------------------
#define ITILE 10
#define QPAD 516
#define SPAD 104
#define ATTN_SMEM ((ITILE*QPAD + 8*QPAD + NHD*ITILE*SPAD) * 4)

__global__ void __launch_bounds__(256)
attn_kernel(const float* __restrict__ qkvbase, const float* __restrict__ As,
            const float* __restrict__ Aa, const int* __restrict__ adj,
            const int* __restrict__ len_list, float* __restrict__ outbuf)
{
    extern __shared__ float dsm[];
    float* q_s = dsm;
    float* kv_s = q_s + ITILE * QPAD;
    float* S_s = kv_s + 8 * QPAD;

    const int i0 = blockIdx.x * ITILE;
    const int b  = blockIdx.y;
    const int z  = blockIdx.z;
    const int st = z >> 1, m = z & 1;
    const float* qkv = qkvbase + (long)st * MROWS * 3072;
    const float* Am = st ? Aa : As;

    const int t = threadIdx.x, h = t >> 5, lane = t & 31;
    const int len = len_list[b];

    for (int idx = t; idx < ITILE * HID; idx += 256) {
        int ii = idx >> 9, c = idx & 511;
        q_s[ii * QPAD + c] = qkv[((long)(b * SEQ + i0 + ii)) * 3072 + m * 1536 + c];
    }
    __syncthreads();

    for (int c0 = 0; c0 < SEQ; c0 += 8) {
        int nr = SEQ - c0; if (nr > 8) nr = 8;
        for (int idx = t; idx < nr * HID; idx += 256) {
            int r = idx >> 9, cc = idx & 511;
            kv_s[r * QPAD + cc] = qkv[((long)(b * SEQ + c0 + r)) * 3072 + m * 1536 + 512 + cc];
        }
        __syncthreads();
        int j = lane >> 2, isub = lane & 3;
        if (j < nr) {
            for (int ii = isub; ii < ITILE; ii += 4) {
                const float4* qr = (const float4*)(q_s + ii * QPAD + h * DK);
                const float4* kr = (const float4*)(kv_s + j * QPAD + h * DK);
                float d = 0.f;
                #pragma unroll
                for (int kk = 0; kk < 16; kk++) {
                    float4 a = qr[kk], c = kr[kk];
                    d += a.x * c.x + a.y * c.y + a.z * c.z + a.w * c.w;
                }
                S_s[(h * ITILE + ii) * SPAD + c0 + j] = d;
            }
        }
        __syncthreads();
    }

    for (int ii = 0; ii < ITILE; ii++) {
        int i = i0 + ii;
        float* Sr = S_s + (h * ITILE + ii) * SPAD;
        const int*   adjrow = adj + ((long)b * SEQ + i) * SEQ;
        const float* Arow   = Am + (((long)b * NHD + h) * SEQ + i) * SEQ;
        float mx = -INFINITY;
        for (int jj = lane; jj < SEQ; jj += 32) {
            float r = Sr[jj];
            bool masked;
            if (jj == i) masked = false;
            else {
                bool same = (adjrow[jj] == 0);
                bool pad  = (jj >= len);
                masked = (m == 0) ? (same || pad) : (!same || pad);
            }
            float sv = masked ? -INFINITY : r * 0.125f * Arow[jj];
            Sr[jj] = sv;
            mx = fmaxf(mx, sv);
        }
        #pragma unroll
        for (int off = 16; off; off >>= 1) mx = fmaxf(mx, __shfl_xor_sync(0xffffffffu, mx, off));
        float se = 0.f;
        for (int jj = lane; jj < SEQ; jj += 32) {
            float e = __expf(Sr[jj] - mx);
            Sr[jj] = e;
            se += e;
        }
        #pragma unroll
        for (int off = 16; off; off >>= 1) se += __shfl_xor_sync(0xffffffffu, se, off);
        float inv = 1.f / se;
        for (int jj = lane; jj < SEQ; jj += 32) Sr[jj] *= inv;
    }

    float o0[ITILE], o1[ITILE];
    #pragma unroll
    for (int ii = 0; ii < ITILE; ii++) { o0[ii] = 0.f; o1[ii] = 0.f; }

    for (int c0 = 0; c0 < SEQ; c0 += 8) {
        int nr = SEQ - c0; if (nr > 8) nr = 8;
        __syncthreads();
        for (int idx = t; idx < nr * HID; idx += 256) {
            int r = idx >> 9, cc = idx & 511;
            kv_s[r * QPAD + cc] = qkv[((long)(b * SEQ + c0 + r)) * 3072 + m * 1536 + 1024 + cc];
        }
        __syncthreads();
        for (int r = 0; r < nr; r++) {
            float2 v2 = *(const float2*)(kv_s + r * QPAD + h * DK + lane * 2);
            int j = c0 + r;
            #pragma unroll
            for (int ii = 0; ii < ITILE; ii++) {
                float p = S_s[(h * ITILE + ii) * SPAD + j];
                o0[ii] += p * v2.x;
                o1[ii] += p * v2.y;
            }
        }
    }

    #pragma unroll
    for (int ii = 0; ii < ITILE; ii++) {
        long orow = (long)z * MROWS + b * SEQ + i0 + ii;
        float2* dst = (float2*)(outbuf + orow * HID + h * DK + lane * 2);
        *dst = make_float2(o0[ii], o1[ii]);
    }
}

// ---------------- residual updates (both streams) -------------------------------
__global__ void update2_kernel(float* __restrict__ sx, float* __restrict__ ax,
                               const float* __restrict__ opj)
{
    int idx = blockIdx.x * 256 + threadIdx.x;
    const int n = MROWS * HID;
    if (idx < n) {
        float v = opj[idx] + opj[idx + n];
        sx[idx] += (v > 0.f ? v : 0.f);
        float w = opj[idx + 2 * n] + opj[idx + 3 * n];
        ax[idx] += (w > 0.f ? w : 0.f);
    }
}

// ---------------- final small-N projection --------------------------------------
__global__ void final_kernel(const float* __restrict__ x0, const float* __restrict__ x,
                             const float* __restrict__ W, const float* __restrict__ bias,
                             float* __restrict__ out, int N)
{
    int row = blockIdx.x;
    __shared__ float xs[HID];
    __shared__ float Wsh[HID * 12];
    int t = threadIdx.x, nt = blockDim.x;
    for (int k = t; k < HID; k += nt) xs[k] = x0[(long)row * HID + k] + x[(long)row * HID + k];
    for (int k = t; k < HID * N; k += nt) Wsh[k] = W[k];
    __syncthreads();
    int col = t >> 5, lane = t & 31;
    float acc = 0.f;
    for (int k = lane; k < HID; k += 32) acc += xs[k] * Wsh[k * N + col];
    #pragma unroll
    for (int off = 16; off; off >>= 1) acc += __shfl_down_sync(0xffffffffu, acc, off);
    if (lane == 0) out[(long)row * N + col] = acc + bias[col];
}

// -----------------------------------------------------------------------------
extern "C" void kernel_launch(void* const* d_in, const int* in_sizes, int n_in,
                              void* d_out, int out_size)
{
    bool dictOrder = (in_sizes[4] == 8);

    const float *sent_x, *act_x, *sent_logits, *act_logits;
    const float *w_sent_t, *b_sent_t, *w_act_t, *b_act_t;
    const float *w_sent_f, *b_sent_f, *w_act_f, *b_act_f;
    const float *sgw1, *sgb1, *sgw2, *sgb2, *agw1, *agb1, *agw2, *agb2, *pos_table;
    const float *s_qkv_w, *s_qkv_b, *s_o_w, *s_o_b;
    const float *a_qkv_w, *a_qkv_b, *a_o_w, *a_o_b;
    const int *len_list, *adj;

    if (dictOrder) {
        sent_x      = (const float*)d_in[0];
        act_x       = (const float*)d_in[1];
        sent_logits = (const float*)d_in[2];
        act_logits  = (const float*)d_in[3];
        len_list    = (const int*)  d_in[4];
        adj         = (const int*)  d_in[5];
        w_sent_t = (const float*)d_in[6];  b_sent_t = (const float*)d_in[7];
        w_act_t  = (const float*)d_in[8];  b_act_t  = (const float*)d_in[9];
        w_sent_f = (const float*)d_in[10]; b_sent_f = (const float*)d_in[11];
        w_act_f  = (const float*)d_in[12]; b_act_f  = (const float*)d_in[13];
        sgw1 = (const float*)d_in[14]; sgb1 = (const float*)d_in[15];
        sgw2 = (const float*)d_in[16]; sgb2 = (const float*)d_in[17];
        agw1 = (const float*)d_in[18]; agb1 = (const float*)d_in[19];
        agw2 = (const float*)d_in[20]; agb2 = (const float*)d_in[21];
        pos_table = (const float*)d_in[22];
        s_qkv_w = (const float*)d_in[23]; s_qkv_b = (const float*)d_in[24];
        s_o_w   = (const float*)d_in[25]; s_o_b   = (const float*)d_in[26];
        a_qkv_w = (const float*)d_in[27]; a_qkv_b = (const float*)d_in[28];
        a_o_w   = (const float*)d_in[29]; a_o_b   = (const float*)d_in[30];
    } else {
        sent_x      = (const float*)d_in[0];
        act_x       = (const float*)d_in[1];
        sent_logits = (const float*)d_in[2];
        act_logits  = (const float*)d_in[3];
        w_sent_t = (const float*)d_in[4];  b_sent_t = (const float*)d_in[5];
        w_act_t  = (const float*)d_in[6];  b_act_t  = (const float*)d_in[7];
        w_sent_f = (const float*)d_in[8];  b_sent_f = (const float*)d_in[9];
        w_act_f  = (const float*)d_in[10]; b_act_f  = (const float*)d_in[11];
        sgw1 = (const float*)d_in[12]; sgb1 = (const float*)d_in[13];
        sgw2 = (const float*)d_in[14]; sgb2 = (const float*)d_in[15];
        agw1 = (const float*)d_in[16]; agb1 = (const float*)d_in[17];
        agw2 = (const float*)d_in[18]; agb2 = (const float*)d_in[19];
        pos_table = (const float*)d_in[20];
        s_qkv_w = (const float*)d_in[21]; s_qkv_b = (const float*)d_in[22];
        s_o_w   = (const float*)d_in[23]; s_o_b   = (const float*)d_in[24];
        a_qkv_w = (const float*)d_in[25]; a_qkv_b = (const float*)d_in[26];
        a_o_w   = (const float*)d_in[27]; a_o_b   = (const float*)d_in[28];
        len_list = (const int*)d_in[29];
        adj      = (const int*)d_in[30];
    }

    float *sx0, *ax0, *sx, *ax, *us, *vs, *ua, *va, *PTs, *PTa, *As, *Aa, *qkv, *att, *opj;
    cudaGetSymbolAddress((void**)&sx0, g_sx0);
    cudaGetSymbolAddress((void**)&ax0, g_ax0);
    cudaGetSymbolAddress((void**)&sx,  g_sx);
    cudaGetSymbolAddress((void**)&ax,  g_ax);
    cudaGetSymbolAddress((void**)&us,  g_us);
    cudaGetSymbolAddress((void**)&vs,  g_vs);
    cudaGetSymbolAddress((void**)&ua,  g_ua);
    cudaGetSymbolAddress((void**)&va,  g_va);
    cudaGetSymbolAddress((void**)&PTs, g_PTs);
    cudaGetSymbolAddress((void**)&PTa, g_PTa);
    cudaGetSymbolAddress((void**)&As,  g_As);
    cudaGetSymbolAddress((void**)&Aa,  g_Aa);
    cudaGetSymbolAddress((void**)&qkv, g_qkv);
    cudaGetSymbolAddress((void**)&att, g_att);
    cudaGetSymbolAddress((void**)&opj, g_opj);

    cudaFuncSetAttribute(attn_kernel, cudaFuncAttributeMaxDynamicSharedMemorySize, ATTN_SMEM);

    dim3 blk128(128), blk256(256);

    // transforms (z=2), fused residual copy
    {
        GemmSets gs = {};
        gs.s[0] = { sent_x, w_sent_t, b_sent_t, sx0, sx };
        gs.s[1] = { act_x,  w_act_t,  b_act_t,  ax0, ax };
        gemm_tc<<<dim3(8, 13, 2), blk128>>>(gs, MROWS, HID, IND);
    }

    uv_kernel<<<800, 512>>>(sent_logits, act_logits, sgw1, agw1);

    // PT = pos_table @ w1[38:550]  (z=2)
    {
        GemmSets gs = {};
        gs.s[0] = { pos_table, sgw1 + 38 * HID, nullptr, PTs, nullptr };
        gs.s[1] = { pos_table, agw1 + 38 * HID, nullptr, PTa, nullptr };
        gemm_tc<<<dim3(8, 4, 2), blk128>>>(gs, 200, HID, HID);
    }

    // generators (z=2 gens, y=8 b, x=20 i-tiles)
    {
        GenSets gn;
        gn.s[0] = { us, vs, PTs, sgb1, sgw2, sgb2, As };
        gn.s[1] = { ua, va, PTa, agb1, agw2, agb2, Aa };
        genA_kernel<<<dim3(SEQ / GIT, BSZ, 2), blk256>>>(gn);
    }

    for (int l = 0; l < 2; l++) {
        // QKV both streams (z=2)
        {
            GemmSets gs = {};
            gs.s[0] = { sx, s_qkv_w + (long)l * 6 * HID * HID, s_qkv_b + (long)l * 3072,
                        qkv, nullptr };
            gs.s[1] = { ax, a_qkv_w + (long)l * 6 * HID * HID, a_qkv_b + (long)l * 3072,
                        qkv + (long)MROWS * 3072, nullptr };
            gemm_tc<<<dim3(48, 13, 2), blk128>>>(gs, MROWS, 3072, HID);
        }
        // attention, both streams + both masks (z=4)
        attn_kernel<<<dim3(SEQ / ITILE, BSZ, 4), blk256, ATTN_SMEM>>>(
            qkv, As, Aa, adj, len_list, att);
        // O-proj (z=4): z = st*2 + m
        {
            GemmSets gs;
            const float* OW[2] = { s_o_w, a_o_w };
            const float* OB[2] = { s_o_b, a_o_b };
            for (int z = 0; z < 4; z++) {
                int st = z >> 1, m = z & 1;
                gs.s[z] = { att + (long)z * MROWS * HID,
                            OW[st] + ((long)l * 2 + m) * HID * HID,
                            OB[st] + ((long)l * 2 + m) * HID,
                            opj + (long)z * MROWS * HID, nullptr };
            }
            gemm_tc<<<dim3(8, 13, 4), blk128>>>(gs, MROWS, HID, HID);
        }
        update2_kernel<<<1600, blk256>>>(sx, ax, opj);
    }

    float* out = (float*)d_out;
    final_kernel<<<800, 7 * 32>>>(sx0, sx, w_sent_f, b_sent_f, out, 7);
    final_kernel<<<800, 12 * 32>>>(ax0, ax, w_act_f, b_act_f, out + MROWS * 7, 12);
}

// round 7
// speedup vs baseline: 1.0031x; 1.0031x over previous
#include <cuda_runtime.h>
#include <math.h>
#include <stdint.h>

#define BSZ 8
#define SEQ 100
#define IND 768
#define HID 512
#define NHD 8
#define DK  64
#define MROWS (BSZ*SEQ)   // 800

// ---------------- scratch ------------------------------------------------------
__device__ float g_sx0[MROWS*HID];
__device__ float g_ax0[MROWS*HID];
__device__ float g_sx [MROWS*HID];
__device__ float g_ax [MROWS*HID];
__device__ float g_us [MROWS*HID];
__device__ float g_vs [MROWS*HID];
__device__ float g_ua [MROWS*HID];
__device__ float g_va [MROWS*HID];
__device__ float g_PTs[200*HID];
__device__ float g_PTa[200*HID];
__device__ float g_As [BSZ*NHD*SEQ*SEQ];
__device__ float g_Aa [BSZ*NHD*SEQ*SEQ];
__device__ float g_qkv[2*MROWS*3072];
__device__ float g_att[4*MROWS*HID];
__device__ float g_opj[4*MROWS*HID];

// ---------------- tf32 helpers -------------------------------------------------
__device__ __forceinline__ void tf32split(float x, float& hi, float& lo) {
    uint32_t h;
    asm("cvt.rna.tf32.f32 %0, %1;" : "=r"(h) : "f"(x));
    hi = __uint_as_float(h);
    float r = x - hi;
    uint32_t l2;
    asm("cvt.rna.tf32.f32 %0, %1;" : "=r"(l2) : "f"(r));
    lo = __uint_as_float(l2);
}

#define MMA8(d, a, b) \
    asm volatile("mma.sync.aligned.m16n8k8.row.col.f32.tf32.tf32.f32 " \
        "{%0,%1,%2,%3}, {%4,%5,%6,%7}, {%8,%9}, {%0,%1,%2,%3};" \
        : "+f"((d)[0]), "+f"((d)[1]), "+f"((d)[2]), "+f"((d)[3]) \
        : "r"((a)[0]), "r"((a)[1]), "r"((a)[2]), "r"((a)[3]), \
          "r"((b)[0]), "r"((b)[1]))

// ---------------- batched pointer sets -----------------------------------------
struct GemmSet  { const float* A; const float* B; const float* bias; float* C; float* C2; };
struct GemmSets { GemmSet s[4]; };

// ---------------- tensor-core GEMM (3xTF32), depth-2 prefetch -------------------
#define PAS 73
#define PBS 67

__global__ void __launch_bounds__(128)
gemm_tc(GemmSets sets, int M, int N, int K)
{
    GemmSet gsel = sets.s[blockIdx.z];
    const float* __restrict__ A = gsel.A;
    const float* __restrict__ B = gsel.B;
    const float* __restrict__ bias = gsel.bias;
    float* __restrict__ C  = gsel.C;
    float* __restrict__ C2 = gsel.C2;

    __shared__ float2 smA[2][16*PAS];
    __shared__ float2 smB[2][16*PBS];

    const int tid = threadIdx.x;
    const int lane = tid & 31, warp = tid >> 5;
    const int wM = warp >> 1, wN = warp & 1;
    const int t4 = lane & 3, g8 = lane >> 2;
    const int row0 = blockIdx.y * 64, col0 = blockIdx.x * 64;

    float acc[2][4][4];
    #pragma unroll
    for (int mt = 0; mt < 2; mt++)
        #pragma unroll
        for (int nt = 0; nt < 4; nt++)
            #pragma unroll
            for (int e = 0; e < 4; e++) acc[mt][nt][e] = 0.f;

    const int KT = K >> 4;
    float4 avA[2][2], avB[2][2];

#define LOAD_T(set, kt) { \
        int k0 = (kt) << 4; \
        _Pragma("unroll") \
        for (int l = 0; l < 2; l++) { \
            int f = tid + (l << 7); \
            int r = f >> 2, kq = f & 3; \
            int gr = row0 + r; \
            avA[set][l] = (gr < M) ? *(const float4*)(A + (long)gr * K + k0 + (kq << 2)) \
                                   : make_float4(0.f, 0.f, 0.f, 0.f); \
            int kr = f >> 4, nq = f & 15; \
            int gn = col0 + (nq << 2); \
            int gidx = gn >> 9; \
            avB[set][l] = *(const float4*)(B + (long)gidx * K * 512 + (long)(k0 + kr) * 512 + (gn & 511)); \
        } }

#define STORE_T(set, buf) { \
        float2* sA = smA[buf]; float2* sB = smB[buf]; \
        _Pragma("unroll") \
        for (int l = 0; l < 2; l++) { \
            int f = tid + (l << 7); \
            int r = f >> 2, kq = f & 3; \
            float ea[4] = {avA[set][l].x, avA[set][l].y, avA[set][l].z, avA[set][l].w}; \
            _Pragma("unroll") \
            for (int e = 0; e < 4; e++) { \
                int k = (kq << 2) + e; \
                float hi, lo; tf32split(ea[e], hi, lo); \
                sA[k * PAS + r] = make_float2(hi, lo); \
            } \
            int kr = f >> 4, nb = (f & 15) << 2; \
            float eb[4] = {avB[set][l].x, avB[set][l].y, avB[set][l].z, avB[set][l].w}; \
            _Pragma("unroll") \
            for (int e = 0; e < 4; e++) { \
                float hi, lo; tf32split(eb[e], hi, lo); \
                sB[kr * PBS + nb + e] = make_float2(hi, lo); \
            } \
        } }

#define COMPUTE_T(buf) { \
        const float2* sA = smA[buf]; const float2* sB = smB[buf]; \
        _Pragma("unroll") \
        for (int ks = 0; ks < 16; ks += 8) { \
            int kb = ks + t4; \
            uint32_t ah[2][4], al[2][4], bh[4][2], bl[4][2]; \
            _Pragma("unroll") \
            for (int mt = 0; mt < 2; mt++) { \
                int bm = wM * 32 + mt * 16 + g8; \
                float2 p0 = sA[kb * PAS + bm]; \
                float2 p1 = sA[kb * PAS + bm + 8]; \
                float2 p2 = sA[(kb + 4) * PAS + bm]; \
                float2 p3 = sA[(kb + 4) * PAS + bm + 8]; \
                ah[mt][0] = __float_as_uint(p0.x); al[mt][0] = __float_as_uint(p0.y); \
                ah[mt][1] = __float_as_uint(p1.x); al[mt][1] = __float_as_uint(p1.y); \
                ah[mt][2] = __float_as_uint(p2.x); al[mt][2] = __float_as_uint(p2.y); \
                ah[mt][3] = __float_as_uint(p3.x); al[mt][3] = __float_as_uint(p3.y); \
            } \
            _Pragma("unroll") \
            for (int nt = 0; nt < 4; nt++) { \
                int bn = wN * 32 + nt * 8 + g8; \
                float2 q0 = sB[kb * PBS + bn]; \
                float2 q1 = sB[(kb + 4) * PBS + bn]; \
                bh[nt][0] = __float_as_uint(q0.x); bl[nt][0] = __float_as_uint(q0.y); \
                bh[nt][1] = __float_as_uint(q1.x); bl[nt][1] = __float_as_uint(q1.y); \
            } \
            _Pragma("unroll") \
            for (int mt = 0; mt < 2; mt++) \
                _Pragma("unroll") \
                for (int nt = 0; nt < 4; nt++) { \
                    MMA8(acc[mt][nt], ah[mt], bh[nt]); \
                    MMA8(acc[mt][nt], ah[mt], bl[nt]); \
                    MMA8(acc[mt][nt], al[mt], bh[nt]); \
                } \
        } }

    LOAD_T(0, 0);
    if (KT > 1) LOAD_T(1, 1);
    STORE_T(0, 0);
    __syncthreads();

    #pragma unroll 1
    for (int kt = 0; kt < KT; kt++) {
        int cur = kt & 1;
        if (kt + 2 < KT) LOAD_T(cur, kt + 2);
        COMPUTE_T(cur);
        if (kt + 1 < KT) STORE_T((kt + 1) & 1, (kt + 1) & 1);
        __syncthreads();
    }

    #pragma unroll
    for (int mt = 0; mt < 2; mt++) {
        int rbase = row0 + wM * 32 + mt * 16;
        #pragma unroll
        for (int nt = 0; nt < 4; nt++) {
            int cbase = col0 + wN * 32 + nt * 8;
            #pragma unroll
            for (int e = 0; e < 4; e++) {
                int r = rbase + g8 + ((e >= 2) ? 8 : 0);
                int c = cbase + t4 * 2 + (e & 1);
                if (r < M) {
                    float v = acc[mt][nt][e];
                    if (bias) v += bias[c];
                    C[(long)r * N + c] = v;
                    if (C2) C2[(long)r * N + c] = v;
                }
            }
        }
    }
#undef LOAD_T
#undef STORE_T
#undef COMPUTE_T
}

// ---------------- u/v projections ----------------------------------------------
__global__ void uv_kernel(const float* __restrict__ sent_logits,
                          const float* __restrict__ act_logits,
                          const float* __restrict__ sgw1,
                          const float* __restrict__ agw1)
{
    int row = blockIdx.x;
    int t = threadIdx.x;
    __shared__ float p[19];
    if (t < 7) p[t] = sent_logits[row * 7 + t];
    else if (t < 19) p[t] = act_logits[row * 12 + (t - 7)];
    __syncthreads();
    float us = 0.f, vs = 0.f, ua = 0.f, va = 0.f;
    #pragma unroll
    for (int k = 0; k < 19; k++) {
        float pk = p[k];
        us += pk * sgw1[k * HID + t];
        vs += pk * sgw1[(19 + k) * HID + t];
        ua += pk * agw1[k * HID + t];
        va += pk * agw1[(19 + k) * HID + t];
    }
    g_us[row * HID + t] = us;
    g_vs[row * HID + t] = vs;
    g_ua[row * HID + t] = ua;
    g_va[row * HID + t] = va;
}

// ---------------- edge-weight generator (i-tiled, vectorized) -------------------
// grid (SEQ/GIT, BSZ, 2 gens), block 256 = 8 warps (warp owns j, strided by 8).
// acc[i][h] per lane over its 16 k's; shfl-reduce; sigmoid on lane 0.
// w2 in smem with stride 9 -> conflict-free LDS.128 (lane*36 words walks banks).
#define GIT 5

struct GenSet  { const float* u; const float* v; const float* PT;
                 const float* b1; const float* w2; const float* b2; float* Aout; };
struct GenSets { GenSet s[2]; };

__global__ void __launch_bounds__(256) genA_kernel(GenSets gsets)
{
    GenSet g = gsets.s[blockIdx.z];
    const int b  = blockIdx.y;
    const int i0 = blockIdx.x * GIT;

    __shared__ float ush[GIT * HID];
    __shared__ float w2s[HID * 9];
    __shared__ float b2s[NHD];

    const int t = threadIdx.x;
    for (int idx = t; idx < GIT * HID; idx += 256) {
        int i = idx >> 9, k = idx & 511;
        ush[idx] = g.u[(long)(b * SEQ + i0 + i) * HID + k] + g.b1[k];
    }
    for (int idx = t; idx < HID * NHD; idx += 256) {
        int k = idx >> 3, h = idx & 7;
        w2s[k * 9 + h] = g.w2[idx];
    }
    if (t < NHD) b2s[t] = g.b2[t];
    __syncthreads();

    const int warp = t >> 5, lane = t & 31;

    for (int j = warp; j < SEQ; j += 8) {
        const float* vrow = g.v + (long)(b * SEQ + j) * HID;
        float acc[GIT][NHD];
        #pragma unroll
        for (int i = 0; i < GIT; i++)
            #pragma unroll
            for (int h = 0; h < NHD; h++) acc[i][h] = 0.f;

        #pragma unroll
        for (int q = 0; q < 4; q++) {
            int k0 = q * 128 + lane * 4;
            float4 v4 = *(const float4*)(vrow + k0);
            float hv[GIT][4];
            #pragma unroll
            for (int i = 0; i < GIT; i++) {
                const float* pr = g.PT + (long)(j - (i0 + i) + 100) * HID;
                float4 p4 = *(const float4*)(pr + k0);
                float4 u4 = *(const float4*)(ush + i * HID + k0);
                hv[i][0] = fmaxf(u4.x + v4.x + p4.x, 0.f);
                hv[i][1] = fmaxf(u4.y + v4.y + p4.y, 0.f);
                hv[i][2] = fmaxf(u4.z + v4.z + p4.z, 0.f);
                hv[i][3] = fmaxf(u4.w + v4.w + p4.w, 0.f);
            }
            #pragma unroll
            for (int e = 0; e < 4; e++) {
                const float* wr = w2s + (k0 + e) * 9;
                float4 wa = *(const float4*)(wr);
                float4 wb = *(const float4*)(wr + 4);
                #pragma unroll
                for (int i = 0; i < GIT; i++) {
                    float hvv = hv[i][e];
                    acc[i][0] += hvv * wa.x; acc[i][1] += hvv * wa.y;
                    acc[i][2] += hvv * wa.z; acc[i][3] += hvv * wa.w;
                    acc[i][4] += hvv * wb.x; acc[i][5] += hvv * wb.y;
                    acc[i][6] += hvv * wb.z; acc[i][7] += hvv * wb.w;
                }
            }
        }

        #pragma unroll
        for (int i = 0; i < GIT; i++) {
            #pragma unroll
            for (int h = 0; h < NHD; h++) {
                float v = acc[i][h];
                v += __shfl_down_sync(0xffffffffu, v, 16);
                v += __shfl_down_sync(0xffffffffu, v, 8);
                v += __shfl_down_sync(0xffffffffu, v, 4);
                v += __shfl_down_sync(0xffffffffu, v, 2);
                v += __shfl_down_sync(0xffffffffu, v, 1);
                if (lane == 0) {
                    float s = v + b2s[h];
                    g.Aout[(((long)b * NHD + h) * SEQ + (i0 + i)) * SEQ + j] =
                        1.f / (1.f + __expf(-s));
                }
            }
        }
    }
}

// ---------------- attention: i-tiled, all heads per block ----------------------
#define ITILE 10
#define QPAD 516
#define SPAD 104
#define ATTN_SMEM ((ITILE*QPAD + 8*QPAD + NHD*ITILE*SPAD) * 4)

__global__ void __launch_bounds__(256)
attn_kernel(const float* __restrict__ qkvbase, const float* __restrict__ As,
            const float* __restrict__ Aa, const int* __restrict__ adj,
            const int* __restrict__ len_list, float* __restrict__ outbuf)
{
    extern __shared__ float dsm[];
    float* q_s = dsm;
    float* kv_s = q_s + ITILE * QPAD;
    float* S_s = kv_s + 8 * QPAD;

    const int i0 = blockIdx.x * ITILE;
    const int b  = blockIdx.y;
    const int z  = blockIdx.z;
    const int st = z >> 1, m = z & 1;
    const float* qkv = qkvbase + (long)st * MROWS * 3072;
    const float* Am = st ? Aa : As;

    const int t = threadIdx.x, h = t >> 5, lane = t & 31;
    const int len = len_list[b];

    for (int idx = t; idx < ITILE * HID; idx += 256) {
        int ii = idx >> 9, c = idx & 511;
        q_s[ii * QPAD + c] = qkv[((long)(b * SEQ + i0 + ii)) * 3072 + m * 1536 + c];
    }
    __syncthreads();

    for (int c0 = 0; c0 < SEQ; c0 += 8) {
        int nr = SEQ - c0; if (nr > 8) nr = 8;
        for (int idx = t; idx < nr * HID; idx += 256) {
            int r = idx >> 9, cc = idx & 511;
            kv_s[r * QPAD + cc] = qkv[((long)(b * SEQ + c0 + r)) * 3072 + m * 1536 + 512 + cc];
        }
        __syncthreads();
        int j = lane >> 2, isub = lane & 3;
        if (j < nr) {
            for (int ii = isub; ii < ITILE; ii += 4) {
                const float4* qr = (const float4*)(q_s + ii * QPAD + h * DK);
                const float4* kr = (const float4*)(kv_s + j * QPAD + h * DK);
                float d = 0.f;
                #pragma unroll
                for (int kk = 0; kk < 16; kk++) {
                    float4 a = qr[kk], c = kr[kk];
                    d += a.x * c.x + a.y * c.y + a.z * c.z + a.w * c.w;
                }
                S_s[(h * ITILE + ii) * SPAD + c0 + j] = d;
            }
        }
        __syncthreads();
    }

    for (int ii = 0; ii < ITILE; ii++) {
        int i = i0 + ii;
        float* Sr = S_s + (h * ITILE + ii) * SPAD;
        const int*   adjrow = adj + ((long)b * SEQ + i) * SEQ;
        const float* Arow   = Am + (((long)b * NHD + h) * SEQ + i) * SEQ;
        float mx = -INFINITY;
        for (int jj = lane; jj < SEQ; jj += 32) {
            float r = Sr[jj];
            bool masked;
            if (jj == i) masked = false;
            else {
                bool same = (adjrow[jj] == 0);
                bool pad  = (jj >= len);
                masked = (m == 0) ? (same || pad) : (!same || pad);
            }
            float sv = masked ? -INFINITY : r * 0.125f * Arow[jj];
            Sr[jj] = sv;
            mx = fmaxf(mx, sv);
        }
        #pragma unroll
        for (int off = 16; off; off >>= 1) mx = fmaxf(mx, __shfl_xor_sync(0xffffffffu, mx, off));
        float se = 0.f;
        for (int jj = lane; jj < SEQ; jj += 32) {
            float e = __expf(Sr[jj] - mx);
            Sr[jj] = e;
            se += e;
        }
        #pragma unroll
        for (int off = 16; off; off >>= 1) se += __shfl_xor_sync(0xffffffffu, se, off);
        float inv = 1.f / se;
        for (int jj = lane; jj < SEQ; jj += 32) Sr[jj] *= inv;
    }

    float o0[ITILE], o1[ITILE];
    #pragma unroll
    for (int ii = 0; ii < ITILE; ii++) { o0[ii] = 0.f; o1[ii] = 0.f; }

    for (int c0 = 0; c0 < SEQ; c0 += 8) {
        int nr = SEQ - c0; if (nr > 8) nr = 8;
        __syncthreads();
        for (int idx = t; idx < nr * HID; idx += 256) {
            int r = idx >> 9, cc = idx & 511;
            kv_s[r * QPAD + cc] = qkv[((long)(b * SEQ + c0 + r)) * 3072 + m * 1536 + 1024 + cc];
        }
        __syncthreads();
        for (int r = 0; r < nr; r++) {
            float2 v2 = *(const float2*)(kv_s + r * QPAD + h * DK + lane * 2);
            int j = c0 + r;
            #pragma unroll
            for (int ii = 0; ii < ITILE; ii++) {
                float p = S_s[(h * ITILE + ii) * SPAD + j];
                o0[ii] += p * v2.x;
                o1[ii] += p * v2.y;
            }
        }
    }

    #pragma unroll
    for (int ii = 0; ii < ITILE; ii++) {
        long orow = (long)z * MROWS + b * SEQ + i0 + ii;
        float2* dst = (float2*)(outbuf + orow * HID + h * DK + lane * 2);
        *dst = make_float2(o0[ii], o1[ii]);
    }
}

// ---------------- residual updates (both streams) -------------------------------
__global__ void update2_kernel(float* __restrict__ sx, float* __restrict__ ax,
                               const float* __restrict__ opj)
{
    int idx = blockIdx.x * 256 + threadIdx.x;
    const int n = MROWS * HID;
    if (idx < n) {
        float v = opj[idx] + opj[idx + n];
        sx[idx] += (v > 0.f ? v : 0.f);
        float w = opj[idx + 2 * n] + opj[idx + 3 * n];
        ax[idx] += (w > 0.f ? w : 0.f);
    }
}

// ---------------- final small-N projection --------------------------------------
__global__ void final_kernel(const float* __restrict__ x0, const float* __restrict__ x,
                             const float* __restrict__ W, const float* __restrict__ bias,
                             float* __restrict__ out, int N)
{
    int row = blockIdx.x;
    __shared__ float xs[HID];
    __shared__ float Wsh[HID * 12];
    int t = threadIdx.x, nt = blockDim.x;
    for (int k = t; k < HID; k += nt) xs[k] = x0[(long)row * HID + k] + x[(long)row * HID + k];
    for (int k = t; k < HID * N; k += nt) Wsh[k] = W[k];
    __syncthreads();
    int col = t >> 5, lane = t & 31;
    float acc = 0.f;
    for (int k = lane; k < HID; k += 32) acc += xs[k] * Wsh[k * N + col];
    #pragma unroll
    for (int off = 16; off; off >>= 1) acc += __shfl_down_sync(0xffffffffu, acc, off);
    if (lane == 0) out[(long)row * N + col] = acc + bias[col];
}

// -----------------------------------------------------------------------------
extern "C" void kernel_launch(void* const* d_in, const int* in_sizes, int n_in,
                              void* d_out, int out_size)
{
    bool dictOrder = (in_sizes[4] == 8);

    const float *sent_x, *act_x, *sent_logits, *act_logits;
    const float *w_sent_t, *b_sent_t, *w_act_t, *b_act_t;
    const float *w_sent_f, *b_sent_f, *w_act_f, *b_act_f;
    const float *sgw1, *sgb1, *sgw2, *sgb2, *agw1, *agb1, *agw2, *agb2, *pos_table;
    const float *s_qkv_w, *s_qkv_b, *s_o_w, *s_o_b;
    const float *a_qkv_w, *a_qkv_b, *a_o_w, *a_o_b;
    const int *len_list, *adj;

    if (dictOrder) {
        sent_x      = (const float*)d_in[0];
        act_x       = (const float*)d_in[1];
        sent_logits = (const float*)d_in[2];
        act_logits  = (const float*)d_in[3];
        len_list    = (const int*)  d_in[4];
        adj         = (const int*)  d_in[5];
        w_sent_t = (const float*)d_in[6];  b_sent_t = (const float*)d_in[7];
        w_act_t  = (const float*)d_in[8];  b_act_t  = (const float*)d_in[9];
        w_sent_f = (const float*)d_in[10]; b_sent_f = (const float*)d_in[11];
        w_act_f  = (const float*)d_in[12]; b_act_f  = (const float*)d_in[13];
        sgw1 = (const float*)d_in[14]; sgb1 = (const float*)d_in[15];
        sgw2 = (const float*)d_in[16]; sgb2 = (const float*)d_in[17];
        agw1 = (const float*)d_in[18]; agb1 = (const float*)d_in[19];
        agw2 = (const float*)d_in[20]; agb2 = (const float*)d_in[21];
        pos_table = (const float*)d_in[22];
        s_qkv_w = (const float*)d_in[23]; s_qkv_b = (const float*)d_in[24];
        s_o_w   = (const float*)d_in[25]; s_o_b   = (const float*)d_in[26];
        a_qkv_w = (const float*)d_in[27]; a_qkv_b = (const float*)d_in[28];
        a_o_w   = (const float*)d_in[29]; a_o_b   = (const float*)d_in[30];
    } else {
        sent_x      = (const float*)d_in[0];
        act_x       = (const float*)d_in[1];
        sent_logits = (const float*)d_in[2];
        act_logits  = (const float*)d_in[3];
        w_sent_t = (const float*)d_in[4];  b_sent_t = (const float*)d_in[5];
        w_act_t  = (const float*)d_in[6];  b_act_t  = (const float*)d_in[7];
        w_sent_f = (const float*)d_in[8];  b_sent_f = (const float*)d_in[9];
        w_act_f  = (const float*)d_in[10]; b_act_f  = (const float*)d_in[11];
        sgw1 = (const float*)d_in[12]; sgb1 = (const float*)d_in[13];
        sgw2 = (const float*)d_in[14]; sgb2 = (const float*)d_in[15];
        agw1 = (const float*)d_in[16]; agb1 = (const float*)d_in[17];
        agw2 = (const float*)d_in[18]; agb2 = (const float*)d_in[19];
        pos_table = (const float*)d_in[20];
        s_qkv_w = (const float*)d_in[21]; s_qkv_b = (const float*)d_in[22];
        s_o_w   = (const float*)d_in[23]; s_o_b   = (const float*)d_in[24];
        a_qkv_w = (const float*)d_in[25]; a_qkv_b = (const float*)d_in[26];
        a_o_w   = (const float*)d_in[27]; a_o_b   = (const float*)d_in[28];
        len_list = (const int*)d_in[29];
        adj      = (const int*)d_in[30];
    }

    float *sx0, *ax0, *sx, *ax, *us, *vs, *ua, *va, *PTs, *PTa, *As, *Aa, *qkv, *att, *opj;
    cudaGetSymbolAddress((void**)&sx0, g_sx0);
    cudaGetSymbolAddress((void**)&ax0, g_ax0);
    cudaGetSymbolAddress((void**)&sx,  g_sx);
    cudaGetSymbolAddress((void**)&ax,  g_ax);
    cudaGetSymbolAddress((void**)&us,  g_us);
    cudaGetSymbolAddress((void**)&vs,  g_vs);
    cudaGetSymbolAddress((void**)&ua,  g_ua);
    cudaGetSymbolAddress((void**)&va,  g_va);
    cudaGetSymbolAddress((void**)&PTs, g_PTs);
    cudaGetSymbolAddress((void**)&PTa, g_PTa);
    cudaGetSymbolAddress((void**)&As,  g_As);
    cudaGetSymbolAddress((void**)&Aa,  g_Aa);
    cudaGetSymbolAddress((void**)&qkv, g_qkv);
    cudaGetSymbolAddress((void**)&att, g_att);
    cudaGetSymbolAddress((void**)&opj, g_opj);

    cudaFuncSetAttribute(attn_kernel, cudaFuncAttributeMaxDynamicSharedMemorySize, ATTN_SMEM);

    dim3 blk128(128), blk256(256);

    // transforms (z=2), fused residual copy
    {
        GemmSets gs = {};
        gs.s[0] = { sent_x, w_sent_t, b_sent_t, sx0, sx };
        gs.s[1] = { act_x,  w_act_t,  b_act_t,  ax0, ax };
        gemm_tc<<<dim3(8, 13, 2), blk128>>>(gs, MROWS, HID, IND);
    }

    uv_kernel<<<800, 512>>>(sent_logits, act_logits, sgw1, agw1);

    // PT = pos_table @ w1[38:550]  (z=2)
    {
        GemmSets gs = {};
        gs.s[0] = { pos_table, sgw1 + 38 * HID, nullptr, PTs, nullptr };
        gs.s[1] = { pos_table, agw1 + 38 * HID, nullptr, PTa, nullptr };
        gemm_tc<<<dim3(8, 4, 2), blk128>>>(gs, 200, HID, HID);
    }

    // generators (z=2 gens, y=8 b, x=20 i-tiles)
    {
        GenSets gn;
        gn.s[0] = { us, vs, PTs, sgb1, sgw2, sgb2, As };
        gn.s[1] = { ua, va, PTa, agb1, agw2, agb2, Aa };
        genA_kernel<<<dim3(SEQ / GIT, BSZ, 2), blk256>>>(gn);
    }

    for (int l = 0; l < 2; l++) {
        // QKV both streams (z=2)
        {
            GemmSets gs = {};
            gs.s[0] = { sx, s_qkv_w + (long)l * 6 * HID * HID, s_qkv_b + (long)l * 3072,
                        qkv, nullptr };
            gs.s[1] = { ax, a_qkv_w + (long)l * 6 * HID * HID, a_qkv_b + (long)l * 3072,
                        qkv + (long)MROWS * 3072, nullptr };
            gemm_tc<<<dim3(48, 13, 2), blk128>>>(gs, MROWS, 3072, HID);
        }
        // attention, both streams + both masks (z=4)
        attn_kernel<<<dim3(SEQ / ITILE, BSZ, 4), blk256, ATTN_SMEM>>>(
            qkv, As, Aa, adj, len_list, att);
        // O-proj (z=4): z = st*2 + m
        {
            GemmSets gs;
            const float* OW[2] = { s_o_w, a_o_w };
            const float* OB[2] = { s_o_b, a_o_b };
            for (int z = 0; z < 4; z++) {
                int st = z >> 1, m = z & 1;
                gs.s[z] = { att + (long)z * MROWS * HID,
                            OW[st] + ((long)l * 2 + m) * HID * HID,
                            OB[st] + ((long)l * 2 + m) * HID,
                            opj + (long)z * MROWS * HID, nullptr };
            }
            gemm_tc<<<dim3(8, 13, 4), blk128>>>(gs, MROWS, HID, HID);
        }
        update2_kernel<<<1600, blk256>>>(sx, ax, opj);
    }

    float* out = (float*)d_out;
    final_kernel<<<800, 7 * 32>>>(sx0, sx, w_sent_f, b_sent_f, out, 7);
    final_kernel<<<800, 12 * 32>>>(ax0, ax, w_act_f, b_act_f, out + MROWS * 7, 12);
}

// round 8
// speedup vs baseline: 1.1441x; 1.1405x over previous
#include <cuda_runtime.h>
#include <math.h>
#include <stdint.h>

#define BSZ 8
#define SEQ 100
#define IND 768
#define HID 512
#define NHD 8
#define DK  64
#define MROWS (BSZ*SEQ)   // 800

// ---------------- scratch ------------------------------------------------------
__device__ float g_sx0[MROWS*HID];
__device__ float g_ax0[MROWS*HID];
__device__ float g_sx [MROWS*HID];
__device__ float g_ax [MROWS*HID];
__device__ float g_us [MROWS*HID];
__device__ float g_vs [MROWS*HID];
__device__ float g_ua [MROWS*HID];
__device__ float g_va [MROWS*HID];
__device__ float g_PTs[200*HID];
__device__ float g_PTa[200*HID];
__device__ float g_As [BSZ*NHD*SEQ*SEQ];
__device__ float g_Aa [BSZ*NHD*SEQ*SEQ];
__device__ float g_qkv[2*MROWS*3072];
__device__ float g_att[4*MROWS*HID];
__device__ float g_opj[4*MROWS*HID];

// ---------------- tf32 helpers -------------------------------------------------
__device__ __forceinline__ void tf32split(float x, float& hi, float& lo) {
    uint32_t h;
    asm("cvt.rna.tf32.f32 %0, %1;" : "=r"(h) : "f"(x));
    hi = __uint_as_float(h);
    float r = x - hi;
    uint32_t l2;
    asm("cvt.rna.tf32.f32 %0, %1;" : "=r"(l2) : "f"(r));
    lo = __uint_as_float(l2);
}

#define MMA8(d, a, b) \
    asm volatile("mma.sync.aligned.m16n8k8.row.col.f32.tf32.tf32.f32 " \
        "{%0,%1,%2,%3}, {%4,%5,%6,%7}, {%8,%9}, {%0,%1,%2,%3};" \
        : "+f"((d)[0]), "+f"((d)[1]), "+f"((d)[2]), "+f"((d)[3]) \
        : "r"((a)[0]), "r"((a)[1]), "r"((a)[2]), "r"((a)[3]), \
          "r"((b)[0]), "r"((b)[1]))

// ---------------- batched pointer sets -----------------------------------------
struct GemmSet  { const float* A; const float* B; const float* bias; float* C; float* C2; };
struct GemmSets { GemmSet s[4]; };

// ---------------- tensor-core GEMM (3xTF32), depth-2 prefetch -------------------
#define PAS 73
#define PBS 67

__global__ void __launch_bounds__(128)
gemm_tc(GemmSets sets, int M, int N, int K)
{
    GemmSet gsel = sets.s[blockIdx.z];
    const float* __restrict__ A = gsel.A;
    const float* __restrict__ B = gsel.B;
    const float* __restrict__ bias = gsel.bias;
    float* __restrict__ C  = gsel.C;
    float* __restrict__ C2 = gsel.C2;

    __shared__ float2 smA[2][16*PAS];
    __shared__ float2 smB[2][16*PBS];

    const int tid = threadIdx.x;
    const int lane = tid & 31, warp = tid >> 5;
    const int wM = warp >> 1, wN = warp & 1;
    const int t4 = lane & 3, g8 = lane >> 2;
    const int row0 = blockIdx.y * 64, col0 = blockIdx.x * 64;

    float acc[2][4][4];
    #pragma unroll
    for (int mt = 0; mt < 2; mt++)
        #pragma unroll
        for (int nt = 0; nt < 4; nt++)
            #pragma unroll
            for (int e = 0; e < 4; e++) acc[mt][nt][e] = 0.f;

    const int KT = K >> 4;
    float4 avA[2][2], avB[2][2];

#define LOAD_T(set, kt) { \
        int k0 = (kt) << 4; \
        _Pragma("unroll") \
        for (int l = 0; l < 2; l++) { \
            int f = tid + (l << 7); \
            int r = f >> 2, kq = f & 3; \
            int gr = row0 + r; \
            avA[set][l] = (gr < M) ? *(const float4*)(A + (long)gr * K + k0 + (kq << 2)) \
                                   : make_float4(0.f, 0.f, 0.f, 0.f); \
            int kr = f >> 4, nq = f & 15; \
            int gn = col0 + (nq << 2); \
            int gidx = gn >> 9; \
            avB[set][l] = *(const float4*)(B + (long)gidx * K * 512 + (long)(k0 + kr) * 512 + (gn & 511)); \
        } }

#define STORE_T(set, buf) { \
        float2* sA = smA[buf]; float2* sB = smB[buf]; \
        _Pragma("unroll") \
        for (int l = 0; l < 2; l++) { \
            int f = tid + (l << 7); \
            int r = f >> 2, kq = f & 3; \
            float ea[4] = {avA[set][l].x, avA[set][l].y, avA[set][l].z, avA[set][l].w}; \
            _Pragma("unroll") \
            for (int e = 0; e < 4; e++) { \
                int k = (kq << 2) + e; \
                float hi, lo; tf32split(ea[e], hi, lo); \
                sA[k * PAS + r] = make_float2(hi, lo); \
            } \
            int kr = f >> 4, nb = (f & 15) << 2; \
            float eb[4] = {avB[set][l].x, avB[set][l].y, avB[set][l].z, avB[set][l].w}; \
            _Pragma("unroll") \
            for (int e = 0; e < 4; e++) { \
                float hi, lo; tf32split(eb[e], hi, lo); \
                sB[kr * PBS + nb + e] = make_float2(hi, lo); \
            } \
        } }

#define COMPUTE_T(buf) { \
        const float2* sA = smA[buf]; const float2* sB = smB[buf]; \
        _Pragma("unroll") \
        for (int ks = 0; ks < 16; ks += 8) { \
            int kb = ks + t4; \
            uint32_t ah[2][4], al[2][4], bh[4][2], bl[4][2]; \
            _Pragma("unroll") \
            for (int mt = 0; mt < 2; mt++) { \
                int bm = wM * 32 + mt * 16 + g8; \
                float2 p0 = sA[kb * PAS + bm]; \
                float2 p1 = sA[kb * PAS + bm + 8]; \
                float2 p2 = sA[(kb + 4) * PAS + bm]; \
                float2 p3 = sA[(kb + 4) * PAS + bm + 8]; \
                ah[mt][0] = __float_as_uint(p0.x); al[mt][0] = __float_as_uint(p0.y); \
                ah[mt][1] = __float_as_uint(p1.x); al[mt][1] = __float_as_uint(p1.y); \
                ah[mt][2] = __float_as_uint(p2.x); al[mt][2] = __float_as_uint(p2.y); \
                ah[mt][3] = __float_as_uint(p3.x); al[mt][3] = __float_as_uint(p3.y); \
            } \
            _Pragma("unroll") \
            for (int nt = 0; nt < 4; nt++) { \
                int bn = wN * 32 + nt * 8 + g8; \
                float2 q0 = sB[kb * PBS + bn]; \
                float2 q1 = sB[(kb + 4) * PBS + bn]; \
                bh[nt][0] = __float_as_uint(q0.x); bl[nt][0] = __float_as_uint(q0.y); \
                bh[nt][1] = __float_as_uint(q1.x); bl[nt][1] = __float_as_uint(q1.y); \
            } \
            _Pragma("unroll") \
            for (int mt = 0; mt < 2; mt++) \
                _Pragma("unroll") \
                for (int nt = 0; nt < 4; nt++) { \
                    MMA8(acc[mt][nt], ah[mt], bh[nt]); \
                    MMA8(acc[mt][nt], ah[mt], bl[nt]); \
                    MMA8(acc[mt][nt], al[mt], bh[nt]); \
                } \
        } }

    LOAD_T(0, 0);
    if (KT > 1) LOAD_T(1, 1);
    STORE_T(0, 0);
    __syncthreads();

    #pragma unroll 1
    for (int kt = 0; kt < KT; kt++) {
        int cur = kt & 1;
        if (kt + 2 < KT) LOAD_T(cur, kt + 2);
        COMPUTE_T(cur);
        if (kt + 1 < KT) STORE_T((kt + 1) & 1, (kt + 1) & 1);
        __syncthreads();
    }

    #pragma unroll
    for (int mt = 0; mt < 2; mt++) {
        int rbase = row0 + wM * 32 + mt * 16;
        #pragma unroll
        for (int nt = 0; nt < 4; nt++) {
            int cbase = col0 + wN * 32 + nt * 8;
            #pragma unroll
            for (int e = 0; e < 4; e++) {
                int r = rbase + g8 + ((e >= 2) ? 8 : 0);
                int c = cbase + t4 * 2 + (e & 1);
                if (r < M) {
                    float v = acc[mt][nt][e];
                    if (bias) v += bias[c];
                    C[(long)r * N + c] = v;
                    if (C2) C2[(long)r * N + c] = v;
                }
            }
        }
    }
#undef LOAD_T
#undef STORE_T
#undef COMPUTE_T
}

// ---------------- u/v projections ----------------------------------------------
__global__ void uv_kernel(const float* __restrict__ sent_logits,
                          const float* __restrict__ act_logits,
                          const float* __restrict__ sgw1,
                          const float* __restrict__ agw1)
{
    int row = blockIdx.x;
    int t = threadIdx.x;
    __shared__ float p[19];
    if (t < 7) p[t] = sent_logits[row * 7 + t];
    else if (t < 19) p[t] = act_logits[row * 12 + (t - 7)];
    __syncthreads();
    float us = 0.f, vs = 0.f, ua = 0.f, va = 0.f;
    #pragma unroll
    for (int k = 0; k < 19; k++) {
        float pk = p[k];
        us += pk * sgw1[k * HID + t];
        vs += pk * sgw1[(19 + k) * HID + t];
        ua += pk * agw1[k * HID + t];
        va += pk * agw1[(19 + k) * HID + t];
    }
    g_us[row * HID + t] = us;
    g_vs[row * HID + t] = vs;
    g_ua[row * HID + t] = ua;
    g_va[row * HID + t] = va;
}

// ---------------- edge-weight generator (GIT=2, reg-budgeted) -------------------
// grid (SEQ/GIT, BSZ, 2 gens), block 256 = 8 warps (warp owns j, strided by 8).
// w2 smem stride 9 -> conflict-free LDS.128. Packed half-warp reduction:
// i=0 reduced in lanes 0-15, i=1 in lanes 16-31 (6 shfl per h instead of 10).
#define GIT 2

struct GenSet  { const float* u; const float* v; const float* PT;
                 const float* b1; const float* w2; const float* b2; float* Aout; };
struct GenSets { GenSet s[2]; };

__global__ void __launch_bounds__(256, 4) genA_kernel(GenSets gsets)
{
    GenSet g = gsets.s[blockIdx.z];
    const int b  = blockIdx.y;
    const int i0 = blockIdx.x * GIT;

    __shared__ float ush[GIT * HID];
    __shared__ float w2s[HID * 9];
    __shared__ float b2s[NHD];

    const int t = threadIdx.x;
    for (int idx = t; idx < GIT * HID; idx += 256) {
        int i = idx >> 9, k = idx & 511;
        ush[idx] = g.u[(long)(b * SEQ + i0 + i) * HID + k] + g.b1[k];
    }
    for (int idx = t; idx < HID * NHD; idx += 256) {
        int k = idx >> 3, h = idx & 7;
        w2s[k * 9 + h] = g.w2[idx];
    }
    if (t < NHD) b2s[t] = g.b2[t];
    __syncthreads();

    const int warp = t >> 5, lane = t & 31;
    const bool loHalf = lane < 16;

    for (int j = warp; j < SEQ; j += 8) {
        const float* vrow = g.v + (long)(b * SEQ + j) * HID;
        float acc[GIT][NHD];
        #pragma unroll
        for (int i = 0; i < GIT; i++)
            #pragma unroll
            for (int h = 0; h < NHD; h++) acc[i][h] = 0.f;

        #pragma unroll
        for (int q = 0; q < 4; q++) {
            int k0 = q * 128 + lane * 4;
            float4 v4 = *(const float4*)(vrow + k0);
            float hv[GIT][4];
            #pragma unroll
            for (int i = 0; i < GIT; i++) {
                const float* pr = g.PT + (long)(j - (i0 + i) + 100) * HID;
                float4 p4 = *(const float4*)(pr + k0);
                float4 u4 = *(const float4*)(ush + i * HID + k0);
                hv[i][0] = fmaxf(u4.x + v4.x + p4.x, 0.f);
                hv[i][1] = fmaxf(u4.y + v4.y + p4.y, 0.f);
                hv[i][2] = fmaxf(u4.z + v4.z + p4.z, 0.f);
                hv[i][3] = fmaxf(u4.w + v4.w + p4.w, 0.f);
            }
            #pragma unroll
            for (int e = 0; e < 4; e++) {
                const float* wr = w2s + (k0 + e) * 9;
                float4 wa = *(const float4*)(wr);
                float4 wb = *(const float4*)(wr + 4);
                #pragma unroll
                for (int i = 0; i < GIT; i++) {
                    float hvv = hv[i][e];
                    acc[i][0] += hvv * wa.x; acc[i][1] += hvv * wa.y;
                    acc[i][2] += hvv * wa.z; acc[i][3] += hvv * wa.w;
                    acc[i][4] += hvv * wb.x; acc[i][5] += hvv * wb.y;
                    acc[i][6] += hvv * wb.z; acc[i][7] += hvv * wb.w;
                }
            }
        }

        // packed reduction: i=0 -> lanes 0-15, i=1 -> lanes 16-31
        #pragma unroll
        for (int h = 0; h < NHD; h++) {
            float a0 = acc[0][h], a1 = acc[1][h];
            float s0 = __shfl_xor_sync(0xffffffffu, a0, 16);
            float s1 = __shfl_xor_sync(0xffffffffu, a1, 16);
            float c = loHalf ? (a0 + s0) : (a1 + s1);
            c += __shfl_xor_sync(0xffffffffu, c, 8);
            c += __shfl_xor_sync(0xffffffffu, c, 4);
            c += __shfl_xor_sync(0xffffffffu, c, 2);
            c += __shfl_xor_sync(0xffffffffu, c, 1);
            if ((lane & 15) == 0) {
                int i = lane >> 4;   // 0 or 1
                float s = c + b2s[h];
                g.Aout[(((long)b * NHD + h) * SEQ + (i0 + i)) * SEQ + j] =
                    1.f / (1.f + __expf(-s));
            }
        }
    }
}

// ---------------- attention: i-tiled, all heads per block ----------------------
#define ITILE 10
#define QPAD 516
#define SPAD 104
#define ATTN_SMEM ((ITILE*QPAD + 8*QPAD + NHD*ITILE*SPAD) * 4)

__global__ void __launch_bounds__(256)
attn_kernel(const float* __restrict__ qkvbase, const float* __restrict__ As,
            const float* __restrict__ Aa, const int* __restrict__ adj,
            const int* __restrict__ len_list, float* __restrict__ outbuf)
{
    extern __shared__ float dsm[];
    float* q_s = dsm;
    float* kv_s = q_s + ITILE * QPAD;
    float* S_s = kv_s + 8 * QPAD;

    const int i0 = blockIdx.x * ITILE;
    const int b  = blockIdx.y;
    const int z  = blockIdx.z;
    const int st = z >> 1, m = z & 1;
    const float* qkv = qkvbase + (long)st * MROWS * 3072;
    const float* Am = st ? Aa : As;

    const int t = threadIdx.x, h = t >> 5, lane = t & 31;
    const int len = len_list[b];

    for (int idx = t; idx < ITILE * HID; idx += 256) {
        int ii = idx >> 9, c = idx & 511;
        q_s[ii * QPAD + c] = qkv[((long)(b * SEQ + i0 + ii)) * 3072 + m * 1536 + c];
    }
    __syncthreads();

    for (int c0 = 0; c0 < SEQ; c0 += 8) {
        int nr = SEQ - c0; if (nr > 8) nr = 8;
        for (int idx = t; idx < nr * HID; idx += 256) {
            int r = idx >> 9, cc = idx & 511;
            kv_s[r * QPAD + cc] = qkv[((long)(b * SEQ + c0 + r)) * 3072 + m * 1536 + 512 + cc];
        }
        __syncthreads();
        int j = lane >> 2, isub = lane & 3;
        if (j < nr) {
            for (int ii = isub; ii < ITILE; ii += 4) {
                const float4* qr = (const float4*)(q_s + ii * QPAD + h * DK);
                const float4* kr = (const float4*)(kv_s + j * QPAD + h * DK);
                float d = 0.f;
                #pragma unroll
                for (int kk = 0; kk < 16; kk++) {
                    float4 a = qr[kk], c = kr[kk];
                    d += a.x * c.x + a.y * c.y + a.z * c.z + a.w * c.w;
                }
                S_s[(h * ITILE + ii) * SPAD + c0 + j] = d;
            }
        }
        __syncthreads();
    }

    for (int ii = 0; ii < ITILE; ii++) {
        int i = i0 + ii;
        float* Sr = S_s + (h * ITILE + ii) * SPAD;
        const int*   adjrow = adj + ((long)b * SEQ + i) * SEQ;
        const float* Arow   = Am + (((long)b * NHD + h) * SEQ + i) * SEQ;
        float mx = -INFINITY;
        for (int jj = lane; jj < SEQ; jj += 32) {
            float r = Sr[jj];
            bool masked;
            if (jj == i) masked = false;
            else {
                bool same = (adjrow[jj] == 0);
                bool pad  = (jj >= len);
                masked = (m == 0) ? (same || pad) : (!same || pad);
            }
            float sv = masked ? -INFINITY : r * 0.125f * Arow[jj];
            Sr[jj] = sv;
            mx = fmaxf(mx, sv);
        }
        #pragma unroll
        for (int off = 16; off; off >>= 1) mx = fmaxf(mx, __shfl_xor_sync(0xffffffffu, mx, off));
        float se = 0.f;
        for (int jj = lane; jj < SEQ; jj += 32) {
            float e = __expf(Sr[jj] - mx);
            Sr[jj] = e;
            se += e;
        }
        #pragma unroll
        for (int off = 16; off; off >>= 1) se += __shfl_xor_sync(0xffffffffu, se, off);
        float inv = 1.f / se;
        for (int jj = lane; jj < SEQ; jj += 32) Sr[jj] *= inv;
    }

    float o0[ITILE], o1[ITILE];
    #pragma unroll
    for (int ii = 0; ii < ITILE; ii++) { o0[ii] = 0.f; o1[ii] = 0.f; }

    for (int c0 = 0; c0 < SEQ; c0 += 8) {
        int nr = SEQ - c0; if (nr > 8) nr = 8;
        __syncthreads();
        for (int idx = t; idx < nr * HID; idx += 256) {
            int r = idx >> 9, cc = idx & 511;
            kv_s[r * QPAD + cc] = qkv[((long)(b * SEQ + c0 + r)) * 3072 + m * 1536 + 1024 + cc];
        }
        __syncthreads();
        for (int r = 0; r < nr; r++) {
            float2 v2 = *(const float2*)(kv_s + r * QPAD + h * DK + lane * 2);
            int j = c0 + r;
            #pragma unroll
            for (int ii = 0; ii < ITILE; ii++) {
                float p = S_s[(h * ITILE + ii) * SPAD + j];
                o0[ii] += p * v2.x;
                o1[ii] += p * v2.y;
            }
        }
    }

    #pragma unroll
    for (int ii = 0; ii < ITILE; ii++) {
        long orow = (long)z * MROWS + b * SEQ + i0 + ii;
        float2* dst = (float2*)(outbuf + orow * HID + h * DK + lane * 2);
        *dst = make_float2(o0[ii], o1[ii]);
    }
}

// ---------------- residual updates (both streams) -------------------------------
__global__ void update2_kernel(float* __restrict__ sx, float* __restrict__ ax,
                               const float* __restrict__ opj)
{
    int idx = blockIdx.x * 256 + threadIdx.x;
    const int n = MROWS * HID;
    if (idx < n) {
        float v = opj[idx] + opj[idx + n];
        sx[idx] += (v > 0.f ? v : 0.f);
        float w = opj[idx + 2 * n] + opj[idx + 3 * n];
        ax[idx] += (w > 0.f ? w : 0.f);
    }
}

// ---------------- final small-N projection --------------------------------------
__global__ void final_kernel(const float* __restrict__ x0, const float* __restrict__ x,
                             const float* __restrict__ W, const float* __restrict__ bias,
                             float* __restrict__ out, int N)
{
    int row = blockIdx.x;
    __shared__ float xs[HID];
    __shared__ float Wsh[HID * 12];
    int t = threadIdx.x, nt = blockDim.x;
    for (int k = t; k < HID; k += nt) xs[k] = x0[(long)row * HID + k] + x[(long)row * HID + k];
    for (int k = t; k < HID * N; k += nt) Wsh[k] = W[k];
    __syncthreads();
    int col = t >> 5, lane = t & 31;
    float acc = 0.f;
    for (int k = lane; k < HID; k += 32) acc += xs[k] * Wsh[k * N + col];
    #pragma unroll
    for (int off = 16; off; off >>= 1) acc += __shfl_down_sync(0xffffffffu, acc, off);
    if (lane == 0) out[(long)row * N + col] = acc + bias[col];
}

// -----------------------------------------------------------------------------
extern "C" void kernel_launch(void* const* d_in, const int* in_sizes, int n_in,
                              void* d_out, int out_size)
{
    bool dictOrder = (in_sizes[4] == 8);

    const float *sent_x, *act_x, *sent_logits, *act_logits;
    const float *w_sent_t, *b_sent_t, *w_act_t, *b_act_t;
    const float *w_sent_f, *b_sent_f, *w_act_f, *b_act_f;
    const float *sgw1, *sgb1, *sgw2, *sgb2, *agw1, *agb1, *agw2, *agb2, *pos_table;
    const float *s_qkv_w, *s_qkv_b, *s_o_w, *s_o_b;
    const float *a_qkv_w, *a_qkv_b, *a_o_w, *a_o_b;
    const int *len_list, *adj;

    if (dictOrder) {
        sent_x      = (const float*)d_in[0];
        act_x       = (const float*)d_in[1];
        sent_logits = (const float*)d_in[2];
        act_logits  = (const float*)d_in[3];
        len_list    = (const int*)  d_in[4];
        adj         = (const int*)  d_in[5];
        w_sent_t = (const float*)d_in[6];  b_sent_t = (const float*)d_in[7];
        w_act_t  = (const float*)d_in[8];  b_act_t  = (const float*)d_in[9];
        w_sent_f = (const float*)d_in[10]; b_sent_f = (const float*)d_in[11];
        w_act_f  = (const float*)d_in[12]; b_act_f  = (const float*)d_in[13];
        sgw1 = (const float*)d_in[14]; sgb1 = (const float*)d_in[15];
        sgw2 = (const float*)d_in[16]; sgb2 = (const float*)d_in[17];
        agw1 = (const float*)d_in[18]; agb1 = (const float*)d_in[19];
        agw2 = (const float*)d_in[20]; agb2 = (const float*)d_in[21];
        pos_table = (const float*)d_in[22];
        s_qkv_w = (const float*)d_in[23]; s_qkv_b = (const float*)d_in[24];
        s_o_w   = (const float*)d_in[25]; s_o_b   = (const float*)d_in[26];
        a_qkv_w = (const float*)d_in[27]; a_qkv_b = (const float*)d_in[28];
        a_o_w   = (const float*)d_in[29]; a_o_b   = (const float*)d_in[30];
    } else {
        sent_x      = (const float*)d_in[0];
        act_x       = (const float*)d_in[1];
        sent_logits = (const float*)d_in[2];
        act_logits  = (const float*)d_in[3];
        w_sent_t = (const float*)d_in[4];  b_sent_t = (const float*)d_in[5];
        w_act_t  = (const float*)d_in[6];  b_act_t  = (const float*)d_in[7];
        w_sent_f = (const float*)d_in[8];  b_sent_f = (const float*)d_in[9];
        w_act_f  = (const float*)d_in[10]; b_act_f  = (const float*)d_in[11];
        sgw1 = (const float*)d_in[12]; sgb1 = (const float*)d_in[13];
        sgw2 = (const float*)d_in[14]; sgb2 = (const float*)d_in[15];
        agw1 = (const float*)d_in[16]; agb1 = (const float*)d_in[17];
        agw2 = (const float*)d_in[18]; agb2 = (const float*)d_in[19];
        pos_table = (const float*)d_in[20];
        s_qkv_w = (const float*)d_in[21]; s_qkv_b = (const float*)d_in[22];
        s_o_w   = (const float*)d_in[23]; s_o_b   = (const float*)d_in[24];
        a_qkv_w = (const float*)d_in[25]; a_qkv_b = (const float*)d_in[26];
        a_o_w   = (const float*)d_in[27]; a_o_b   = (const float*)d_in[28];
        len_list = (const int*)d_in[29];
        adj      = (const int*)d_in[30];
    }

    float *sx0, *ax0, *sx, *ax, *us, *vs, *ua, *va, *PTs, *PTa, *As, *Aa, *qkv, *att, *opj;
    cudaGetSymbolAddress((void**)&sx0, g_sx0);
    cudaGetSymbolAddress((void**)&ax0, g_ax0);
    cudaGetSymbolAddress((void**)&sx,  g_sx);
    cudaGetSymbolAddress((void**)&ax,  g_ax);
    cudaGetSymbolAddress((void**)&us,  g_us);
    cudaGetSymbolAddress((void**)&vs,  g_vs);
    cudaGetSymbolAddress((void**)&ua,  g_ua);
    cudaGetSymbolAddress((void**)&va,  g_va);
    cudaGetSymbolAddress((void**)&PTs, g_PTs);
    cudaGetSymbolAddress((void**)&PTa, g_PTa);
    cudaGetSymbolAddress((void**)&As,  g_As);
    cudaGetSymbolAddress((void**)&Aa,  g_Aa);
    cudaGetSymbolAddress((void**)&qkv, g_qkv);
    cudaGetSymbolAddress((void**)&att, g_att);
    cudaGetSymbolAddress((void**)&opj, g_opj);

    cudaFuncSetAttribute(attn_kernel, cudaFuncAttributeMaxDynamicSharedMemorySize, ATTN_SMEM);

    dim3 blk128(128), blk256(256);

    // transforms (z=2), fused residual copy
    {
        GemmSets gs = {};
        gs.s[0] = { sent_x, w_sent_t, b_sent_t, sx0, sx };
        gs.s[1] = { act_x,  w_act_t,  b_act_t,  ax0, ax };
        gemm_tc<<<dim3(8, 13, 2), blk128>>>(gs, MROWS, HID, IND);
    }

    uv_kernel<<<800, 512>>>(sent_logits, act_logits, sgw1, agw1);

    // PT = pos_table @ w1[38:550]  (z=2)
    {
        GemmSets gs = {};
        gs.s[0] = { pos_table, sgw1 + 38 * HID, nullptr, PTs, nullptr };
        gs.s[1] = { pos_table, agw1 + 38 * HID, nullptr, PTa, nullptr };
        gemm_tc<<<dim3(8, 4, 2), blk128>>>(gs, 200, HID, HID);
    }

    // generators (z=2 gens, y=8 b, x=50 i-tiles)
    {
        GenSets gn;
        gn.s[0] = { us, vs, PTs, sgb1, sgw2, sgb2, As };
        gn.s[1] = { ua, va, PTa, agb1, agw2, agb2, Aa };
        genA_kernel<<<dim3(SEQ / GIT, BSZ, 2), blk256>>>(gn);
    }

    for (int l = 0; l < 2; l++) {
        // QKV both streams (z=2)
        {
            GemmSets gs = {};
            gs.s[0] = { sx, s_qkv_w + (long)l * 6 * HID * HID, s_qkv_b + (long)l * 3072,
                        qkv, nullptr };
            gs.s[1] = { ax, a_qkv_w + (long)l * 6 * HID * HID, a_qkv_b + (long)l * 3072,
                        qkv + (long)MROWS * 3072, nullptr };
            gemm_tc<<<dim3(48, 13, 2), blk128>>>(gs, MROWS, 3072, HID);
        }
        // attention, both streams + both masks (z=4)
        attn_kernel<<<dim3(SEQ / ITILE, BSZ, 4), blk256, ATTN_SMEM>>>(
            qkv, As, Aa, adj, len_list, att);
        // O-proj (z=4): z = st*2 + m
        {
            GemmSets gs;
            const float* OW[2] = { s_o_w, a_o_w };
            const float* OB[2] = { s_o_b, a_o_b };
            for (int z = 0; z < 4; z++) {
                int st = z >> 1, m = z & 1;
                gs.s[z] = { att + (long)z * MROWS * HID,
                            OW[st] + ((long)l * 2 + m) * HID * HID,
                            OB[st] + ((long)l * 2 + m) * HID,
                            opj + (long)z * MROWS * HID, nullptr };
            }
            gemm_tc<<<dim3(8, 13, 4), blk128>>>(gs, MROWS, HID, HID);
        }
        update2_kernel<<<1600, blk256>>>(sx, ax, opj);
    }

    float* out = (float*)d_out;
    final_kernel<<<800, 7 * 32>>>(sx0, sx, w_sent_f, b_sent_f, out, 7);
    final_kernel<<<800, 12 * 32>>>(ax0, ax, w_act_f, b_act_f, out + MROWS * 7, 12);
}